// round 9
// baseline (speedup 1.0000x reference)
#include <cuda_runtime.h>
#include <cuda_bf16.h>
#include <math.h>

#define PCAP 128
#define CCAP 48
#define NEG_INF (-3.4e38f)

__device__ __constant__ float c_cos[32] = {
    1.0f, 0.5403023058681398f, -0.4161468365471424f, -0.9899924966004454f,
    -0.6536436208636119f, 0.2836621854632263f, 0.9601702866503661f, 0.7539022543433046f,
    -0.14550003380861354f, -0.9111302618846769f, -0.8390715290764524f, 0.004425697988050785f,
    0.8438539587324921f, 0.9074467814501962f, 0.13673721820783361f, -0.7596879128588213f,
    -0.9576594803233847f, -0.2751633380515979f, 0.6603167082440802f, 0.9887046181866692f,
    0.40808206181339196f, -0.5477292602242684f, -0.9999608263946371f, -0.5328330203333975f,
    0.424179007336997f, 0.9912028118634736f, 0.6469193223286404f, -0.2921388087338362f,
    -0.9626058663135666f, -0.7480575296890004f, 0.15425144988758405f, 0.9147423578045313f
};
__device__ __constant__ float c_sin[32] = {
    0.0f, 0.8414709848078965f, 0.9092974268256817f, 0.1411200080598672f,
    -0.7568024953079282f, -0.9589242746631385f, -0.27941549819892586f, 0.6569865987187891f,
    0.9893582466233818f, 0.4121184852417566f, -0.5440211108893698f, -0.9999902065507035f,
    -0.5365729180004349f, 0.4201670368266409f, 0.9906073556948704f, 0.6502878401571168f,
    -0.2879033166650653f, -0.9613974918795568f, -0.7509872467716762f, 0.14987720966295234f,
    0.9129452507276277f, 0.8366556385360561f, -0.008851309290403876f, -0.8462204041751706f,
    -0.9055783620066239f, -0.13235175009777303f, 0.7625584504796028f, 0.956375928404503f,
    0.27090578830786904f, -0.6636338842129675f, -0.9880316240928618f, -0.40403764532307057f
};

// 128 blocks x 512 threads. block -> (b = blk>>3, chunk = blk&7; 128 tokens).
// Phase 1 on warps 0-3 (one per head); phase 2: thread = (token, head) quad.
__global__ void __launch_bounds__(512, 1)
k_all(const int* __restrict__ tok,
      const float* __restrict__ embed,
      const float* __restrict__ inw,
      const float* __restrict__ postw,
      const float* __restrict__ finw,
      const float* __restrict__ qnw,
      const float* __restrict__ knw,
      const float* __restrict__ kp,
      const float* __restrict__ vp,
      const float* __restrict__ qp,
      const float* __restrict__ op,
      const float* __restrict__ gp,
      const float* __restrict__ upw,
      const float* __restrict__ dp,
      float* __restrict__ out) {
    int tid = threadIdx.x;
    int lane = tid & 31, wid = tid >> 5;
    int b = blockIdx.x >> 3;
    int t0 = (blockIdx.x & 7) << 7;
    int tmax = t0 + 127;

    __shared__ int    s_tok[1024];
    __shared__ float  s_emb[30];
    __shared__ float4 s_w[4][10];
    __shared__ float2 s_pool[4][PCAP];
    __shared__ int    s_pn[4];
    __shared__ float2 s_cp[4][CCAP];
    __shared__ int    s_cn[4];

    // ---------- phase 0: independent loads / tables ----------
    if (tid < 4) s_pn[tid] = 0;

    if (tid < 256) {   // stage full token row (256 x int4)
        const int4* rowv = (const int4*)(tok + b * 1024);
        ((int4*)s_tok)[tid] = rowv[tid];
    }
    if (tid < 30) s_emb[tid] = embed[tid];

    // folded v * o_proj table per (head, digit)
    if (tid >= 256 && tid < 296) {
        int q = tid - 256;
        int h = q / 10, dd = q % 10;
        float e0 = embed[3 * dd], e1 = embed[3 * dd + 1], e2 = embed[3 * dd + 2];
        float vv = (e0 * e0 + e1 * e1 + e2 * e2) * (1.0f / 3.0f);
        float rr = rsqrtf(vv + 1e-6f);
        float y0 = e0 * rr * inw[0], y1 = e1 * rr * inw[1], y2 = e2 * rr * inw[2];
        float v0 = vp[0] * y0 + vp[1] * y1 + vp[2] * y2;
        float v1 = vp[3] * y0 + vp[4] * y1 + vp[5] * y2;
        float w0 = v0 * op[0 * 8 + 2 * h] + v1 * op[0 * 8 + 2 * h + 1];
        float w1 = v0 * op[1 * 8 + 2 * h] + v1 * op[1 * 8 + 2 * h + 1];
        float w2 = v0 * op[2 * 8 + 2 * h] + v1 * op[2 * 8 + 2 * h + 1];
        s_w[h][dd] = make_float4(w0, w1, w2, 0.0f);
    }

    // ---------- phase 1: warps 0-3, head h = wid ----------
    if (wid < 4) {
        int h = wid;
        float A, B;
        {
            float e0 = embed[0], e1 = embed[1], e2 = embed[2];
            float vv = (e0 * e0 + e1 * e1 + e2 * e2) * (1.0f / 3.0f);
            float rr = rsqrtf(vv + 1e-6f);
            float xl0 = e0 * rr * inw[0], xl1 = e1 * rr * inw[1], xl2 = e2 * rr * inw[2];
            float k0 = kp[0] * xl0 + kp[1] * xl1 + kp[2] * xl2;
            float k1 = kp[3] * xl0 + kp[4] * xl1 + kp[5] * xl2;
            float rk = rsqrtf((k0 * k0 + k1 * k1) * 0.5f + 1e-6f);
            float kn0 = k0 * rk * knw[0], kn1 = k1 * rk * knw[1];
            const float* q0r = qp + (2 * h) * 3;
            const float* q1r = qp + (2 * h + 1) * 3;
            float q0 = q0r[0] * xl0 + q0r[1] * xl1 + q0r[2] * xl2;
            float q1 = q1r[0] * xl0 + q1r[1] * xl1 + q1r[2] * xl2;
            float rq = rsqrtf((q0 * q0 + q1 * q1) * 0.5f + 1e-6f);
            float qn0 = q0 * rq * qnw[0], qn1 = q1 * rq * qnw[1];
            float P = (qn0 * kn0 + qn1 * kn1) * 0.70710678118654752f;
            float X = (qn0 * kn1 - qn1 * kn0) * 0.70710678118654752f;
            float cb, sb;
            sincosf((float)(lane * 32), &sb, &cb);
            A = P * cb + X * sb;
            B = X * cb - P * sb;
        }
        // lane covers delta in [lane*32, lane*32+32)
        float lm = NEG_INF;
        #pragma unroll
        for (int i = 0; i < 32; i++)
            lm = fmaxf(lm, A * c_cos[i] + B * c_sin[i]);
        float sc = lm;
        #pragma unroll
        for (int off = 1; off < 32; off <<= 1) {
            float v = __shfl_up_sync(0xffffffffu, sc, off);
            if (lane >= off) sc = fmaxf(sc, v);
        }
        float ex = __shfl_up_sync(0xffffffffu, sc, 1);
        float run = (lane == 0) ? NEG_INF : ex;
        int base = lane * 32;
        if (base <= tmax) {
            #pragma unroll
            for (int i = 0; i < 32; i++) {
                float f = A * c_cos[i] + B * c_sin[i];
                if (f >= run - 13.0f && base + i <= tmax) {
                    int idx = atomicAdd(&s_pn[h], 1);
                    if (idx < PCAP)
                        s_pool[h][idx] = make_float2((float)(base + i), f);
                }
                run = fmaxf(run, f);
            }
        }
    }
    __syncthreads();

    // ---------- phase 1b: block-level prune + compaction (warps 0-3) --------
    if (wid < 4) {
        int h = wid;
        int n = min(s_pn[h], PCAP);
        float m = NEG_INF;
        for (int e = lane; e < n; e += 32) {
            float2 p = s_pool[h][e];
            if ((int)p.x <= t0) m = fmaxf(m, p.y);
        }
        #pragma unroll
        for (int off = 16; off; off >>= 1)
            m = fmaxf(m, __shfl_xor_sync(0xffffffffu, m, off));
        float cut = m - 13.0f;
        int outp = 0;
        for (int cb = 0; cb < n; cb += 32) {
            int e = cb + lane;
            bool keep = false;
            float2 p;
            if (e < n) { p = s_pool[h][e]; keep = (p.y >= cut); }
            unsigned msk = __ballot_sync(0xffffffffu, keep);
            if (keep) {
                int pos = outp + __popc(msk & ((1u << lane) - 1));
                if (pos < CCAP) s_cp[h][pos] = p;
            }
            outp += __popc(msk);
        }
        if (lane == 0) s_cn[h] = min(outp, CCAP);
    }
    __syncthreads();

    // ---------- phase 2: thread = (token, head); quad-reduce heads ----------
    int t = t0 + (tid >> 2);
    int h = tid & 3;
    int d = s_tok[t];
    float x0 = s_emb[3 * d], x1 = s_emb[3 * d + 1], x2 = s_emb[3 * d + 2];

    float cx0, cx1, cx2;
    {
        int n = s_cn[h];
        float M = NEG_INF;
        for (int j = 0; j < n; j++) {
            float2 e = s_cp[h][j];
            if ((int)e.x <= t) M = fmaxf(M, e.y);
        }
        float thr = M - 13.0f;
        float sum = 0.0f, c0 = 0.0f, c1 = 0.0f, c2 = 0.0f;
        for (int j = 0; j < n; j++) {
            float2 e = s_cp[h][j];
            int dj = (int)e.x;
            if (dj <= t && e.y > thr) {
                float p = __expf(e.y - M);
                sum += p;
                float4 w = s_w[h][s_tok[t - dj]];
                c0 += p * w.x;
                c1 += p * w.y;
                c2 += p * w.z;
            }
        }
        float inv = 1.0f / sum;
        cx0 = c0 * inv;
        cx1 = c1 * inv;
        cx2 = c2 * inv;
    }
    #pragma unroll
    for (int off = 1; off < 4; off <<= 1) {
        cx0 += __shfl_xor_sync(0xffffffffu, cx0, off);
        cx1 += __shfl_xor_sync(0xffffffffu, cx1, off);
        cx2 += __shfl_xor_sync(0xffffffffu, cx2, off);
    }
    x0 += cx0;
    x1 += cx1;
    x2 += cx2;

    // ---------- epilogue (redundant per quad; stores split by lane) ----------
    float var = (x0 * x0 + x1 * x1 + x2 * x2) * (1.0f / 3.0f);
    float r = rsqrtf(var + 1e-6f);
    float y0 = x0 * r * postw[0];
    float y1 = x1 * r * postw[1];
    float y2 = x2 * r * postw[2];
    #pragma unroll
    for (int j = 0; j < 4; j++) {
        float g = gp[j * 3] * y0 + gp[j * 3 + 1] * y1 + gp[j * 3 + 2] * y2;
        float u = upw[j * 3] * y0 + upw[j * 3 + 1] * y1 + upw[j * 3 + 2] * y2;
        float sil = g / (1.0f + __expf(-g));
        float hh = sil * u;
        x0 += dp[0 * 4 + j] * hh;
        x1 += dp[1 * 4 + j] * hh;
        x2 += dp[2 * 4 + j] * hh;
    }
    float var2 = (x0 * x0 + x1 * x1 + x2 * x2) * (1.0f / 3.0f);
    float r2 = rsqrtf(var2 + 1e-6f);
    float z0 = x0 * r2 * finw[0];
    float z1 = x1 * r2 * finw[1];
    float z2 = x2 * r2 * finw[2];

    float lg[10];
    #pragma unroll
    for (int dd = 0; dd < 10; dd++)
        lg[dd] = z0 * s_emb[3 * dd] + z1 * s_emb[3 * dd + 1] + z2 * s_emb[3 * dd + 2];

    float2* o2 = (float2*)(out + (size_t)(b * 1024 + t) * 10);
    o2[h] = make_float2(lg[2 * h], lg[2 * h + 1]);
    if (h == 0) o2[4] = make_float2(lg[8], lg[9]);
}

extern "C" void kernel_launch(void* const* d_in, const int* in_sizes, int n_in,
                              void* d_out, int out_size) {
    const int*   tok   = (const int*)d_in[0];
    const float* embed = (const float*)d_in[1];
    const float* inw   = (const float*)d_in[2];
    const float* postw = (const float*)d_in[3];
    const float* finw  = (const float*)d_in[4];
    const float* qnw   = (const float*)d_in[5];
    const float* knw   = (const float*)d_in[6];
    const float* kp    = (const float*)d_in[7];
    const float* vp    = (const float*)d_in[8];
    const float* qp    = (const float*)d_in[9];
    const float* op    = (const float*)d_in[10];
    const float* gp    = (const float*)d_in[11];
    const float* upw   = (const float*)d_in[12];
    const float* dp    = (const float*)d_in[13];
    float* out = (float*)d_out;

    k_all<<<128, 512>>>(tok, embed, inw, postw, finw, qnw, knw,
                        kp, vp, qp, op, gp, upw, dp, out);
}

// round 10
// speedup vs baseline: 1.0488x; 1.0488x over previous
#include <cuda_runtime.h>
#include <cuda_bf16.h>
#include <math.h>

#define PCAP 128
#define CCAP 48
#define NEG_INF (-3.4e38f)

__device__ __constant__ float c_cos[32] = {
    1.0f, 0.5403023058681398f, -0.4161468365471424f, -0.9899924966004454f,
    -0.6536436208636119f, 0.2836621854632263f, 0.9601702866503661f, 0.7539022543433046f,
    -0.14550003380861354f, -0.9111302618846769f, -0.8390715290764524f, 0.004425697988050785f,
    0.8438539587324921f, 0.9074467814501962f, 0.13673721820783361f, -0.7596879128588213f,
    -0.9576594803233847f, -0.2751633380515979f, 0.6603167082440802f, 0.9887046181866692f,
    0.40808206181339196f, -0.5477292602242684f, -0.9999608263946371f, -0.5328330203333975f,
    0.424179007336997f, 0.9912028118634736f, 0.6469193223286404f, -0.2921388087338362f,
    -0.9626058663135666f, -0.7480575296890004f, 0.15425144988758405f, 0.9147423578045313f
};
__device__ __constant__ float c_sin[32] = {
    0.0f, 0.8414709848078965f, 0.9092974268256817f, 0.1411200080598672f,
    -0.7568024953079282f, -0.9589242746631385f, -0.27941549819892586f, 0.6569865987187891f,
    0.9893582466233818f, 0.4121184852417566f, -0.5440211108893698f, -0.9999902065507035f,
    -0.5365729180004349f, 0.4201670368266409f, 0.9906073556948704f, 0.6502878401571168f,
    -0.2879033166650653f, -0.9613974918795568f, -0.7509872467716762f, 0.14987720966295234f,
    0.9129452507276277f, 0.8366556385360561f, -0.008851309290403876f, -0.8462204041751706f,
    -0.9055783620066239f, -0.13235175009777303f, 0.7625584504796028f, 0.956375928404503f,
    0.27090578830786904f, -0.6636338842129675f, -0.9880316240928618f, -0.40403764532307057f
};

// 128 blocks x 512 threads, 2 blocks/SM. block -> (b = blk>>3, chunk = blk&7).
// Phase 1 on warps 0-3 (one per head); phase 2: thread = (token, head) quad.
__global__ void __launch_bounds__(512, 2)
k_all(const int* __restrict__ tok,
      const float* __restrict__ embed,
      const float* __restrict__ inw,
      const float* __restrict__ postw,
      const float* __restrict__ finw,
      const float* __restrict__ qnw,
      const float* __restrict__ knw,
      const float* __restrict__ kp,
      const float* __restrict__ vp,
      const float* __restrict__ qp,
      const float* __restrict__ op,
      const float* __restrict__ gp,
      const float* __restrict__ upw,
      const float* __restrict__ dp,
      float* __restrict__ out) {
    int tid = threadIdx.x;
    int lane = tid & 31, wid = tid >> 5;
    int b = blockIdx.x >> 3;
    int t0 = (blockIdx.x & 7) << 7;
    int tmax = t0 + 127;

    __shared__ int    s_tok[1024];
    __shared__ float  s_emb[30];
    __shared__ float4 s_w[4][10];
    __shared__ float2 s_pool[4][PCAP];
    __shared__ int    s_pn[4];
    __shared__ float2 s_cp[4][CCAP];
    __shared__ int    s_cn[4];

    // ---------- phase 0: independent loads / tables ----------
    if (tid < 4) s_pn[tid] = 0;

    if ((tid & 1) == 0) {   // stage full token row: 256 int4 over even threads
        const int4* rowv = (const int4*)(tok + b * 1024);
        ((int4*)s_tok)[tid >> 1] = rowv[tid >> 1];
    }
    if (tid < 30) s_emb[tid] = embed[tid];

    // folded v * o_proj table per (head, digit)
    if (tid >= 256 && tid < 296) {
        int q = tid - 256;
        int h = q / 10, dd = q % 10;
        float e0 = embed[3 * dd], e1 = embed[3 * dd + 1], e2 = embed[3 * dd + 2];
        float vv = (e0 * e0 + e1 * e1 + e2 * e2) * (1.0f / 3.0f);
        float rr = rsqrtf(vv + 1e-6f);
        float y0 = e0 * rr * inw[0], y1 = e1 * rr * inw[1], y2 = e2 * rr * inw[2];
        float v0 = vp[0] * y0 + vp[1] * y1 + vp[2] * y2;
        float v1 = vp[3] * y0 + vp[4] * y1 + vp[5] * y2;
        float w0 = v0 * op[0 * 8 + 2 * h] + v1 * op[0 * 8 + 2 * h + 1];
        float w1 = v0 * op[1 * 8 + 2 * h] + v1 * op[1 * 8 + 2 * h + 1];
        float w2 = v0 * op[2 * 8 + 2 * h] + v1 * op[2 * 8 + 2 * h + 1];
        s_w[h][dd] = make_float4(w0, w1, w2, 0.0f);
    }

    // ---------- phase 1: warps 0-3, head h = wid ----------
    if (wid < 4) {
        int h = wid;
        float A, B;
        {
            float e0 = embed[0], e1 = embed[1], e2 = embed[2];
            float vv = (e0 * e0 + e1 * e1 + e2 * e2) * (1.0f / 3.0f);
            float rr = rsqrtf(vv + 1e-6f);
            float xl0 = e0 * rr * inw[0], xl1 = e1 * rr * inw[1], xl2 = e2 * rr * inw[2];
            float k0 = kp[0] * xl0 + kp[1] * xl1 + kp[2] * xl2;
            float k1 = kp[3] * xl0 + kp[4] * xl1 + kp[5] * xl2;
            float rk = rsqrtf((k0 * k0 + k1 * k1) * 0.5f + 1e-6f);
            float kn0 = k0 * rk * knw[0], kn1 = k1 * rk * knw[1];
            const float* q0r = qp + (2 * h) * 3;
            const float* q1r = qp + (2 * h + 1) * 3;
            float q0 = q0r[0] * xl0 + q0r[1] * xl1 + q0r[2] * xl2;
            float q1 = q1r[0] * xl0 + q1r[1] * xl1 + q1r[2] * xl2;
            float rq = rsqrtf((q0 * q0 + q1 * q1) * 0.5f + 1e-6f);
            float qn0 = q0 * rq * qnw[0], qn1 = q1 * rq * qnw[1];
            float P = (qn0 * kn0 + qn1 * kn1) * 0.70710678118654752f;
            float X = (qn0 * kn1 - qn1 * kn0) * 0.70710678118654752f;
            float cb, sb;
            sincosf((float)(lane * 32), &sb, &cb);
            A = P * cb + X * sb;
            B = X * cb - P * sb;
        }
        // lane covers delta in [lane*32, lane*32+32)
        float lm = NEG_INF;
        #pragma unroll
        for (int i = 0; i < 32; i++)
            lm = fmaxf(lm, A * c_cos[i] + B * c_sin[i]);
        float sc = lm;
        #pragma unroll
        for (int off = 1; off < 32; off <<= 1) {
            float v = __shfl_up_sync(0xffffffffu, sc, off);
            if (lane >= off) sc = fmaxf(sc, v);
        }
        float ex = __shfl_up_sync(0xffffffffu, sc, 1);
        float run = (lane == 0) ? NEG_INF : ex;
        int base = lane * 32;
        if (base <= tmax) {
            #pragma unroll
            for (int i = 0; i < 32; i++) {
                float f = A * c_cos[i] + B * c_sin[i];
                if (f >= run - 13.0f && base + i <= tmax) {
                    int idx = atomicAdd(&s_pn[h], 1);
                    if (idx < PCAP)
                        s_pool[h][idx] = make_float2((float)(base + i), f);
                }
                run = fmaxf(run, f);
            }
        }
    }
    __syncthreads();

    // ---------- phase 1b: block-level prune + compaction (warps 0-3) --------
    if (wid < 4) {
        int h = wid;
        int n = min(s_pn[h], PCAP);
        float m = NEG_INF;
        for (int e = lane; e < n; e += 32) {
            float2 p = s_pool[h][e];
            if ((int)p.x <= t0) m = fmaxf(m, p.y);
        }
        #pragma unroll
        for (int off = 16; off; off >>= 1)
            m = fmaxf(m, __shfl_xor_sync(0xffffffffu, m, off));
        float cut = m - 13.0f;
        int outp = 0;
        for (int cb = 0; cb < n; cb += 32) {
            int e = cb + lane;
            bool keep = false;
            float2 p;
            if (e < n) { p = s_pool[h][e]; keep = (p.y >= cut); }
            unsigned msk = __ballot_sync(0xffffffffu, keep);
            if (keep) {
                int pos = outp + __popc(msk & ((1u << lane) - 1));
                if (pos < CCAP) s_cp[h][pos] = p;
            }
            outp += __popc(msk);
        }
        if (lane == 0) s_cn[h] = min(outp, CCAP);
    }
    __syncthreads();

    // ---------- phase 2: thread = (token, head); quad-reduce heads ----------
    int t = t0 + (tid >> 2);
    int h = tid & 3;
    int d = s_tok[t];
    float x0 = s_emb[3 * d], x1 = s_emb[3 * d + 1], x2 = s_emb[3 * d + 2];

    float cx0, cx1, cx2;
    {
        int n = s_cn[h];
        float M = NEG_INF;
        for (int j = 0; j < n; j++) {
            float2 e = s_cp[h][j];
            if ((int)e.x <= t) M = fmaxf(M, e.y);
        }
        float thr = M - 13.0f;
        float sum = 0.0f, c0 = 0.0f, c1 = 0.0f, c2 = 0.0f;
        for (int j = 0; j < n; j++) {
            float2 e = s_cp[h][j];
            int dj = (int)e.x;
            if (dj <= t && e.y > thr) {
                float p = __expf(e.y - M);
                sum += p;
                float4 w = s_w[h][s_tok[t - dj]];
                c0 += p * w.x;
                c1 += p * w.y;
                c2 += p * w.z;
            }
        }
        float inv = 1.0f / sum;
        cx0 = c0 * inv;
        cx1 = c1 * inv;
        cx2 = c2 * inv;
    }
    #pragma unroll
    for (int off = 1; off < 4; off <<= 1) {
        cx0 += __shfl_xor_sync(0xffffffffu, cx0, off);
        cx1 += __shfl_xor_sync(0xffffffffu, cx1, off);
        cx2 += __shfl_xor_sync(0xffffffffu, cx2, off);
    }
    x0 += cx0;
    x1 += cx1;
    x2 += cx2;

    // ---------- epilogue (redundant per quad; stores split by lane) ----------
    float var = (x0 * x0 + x1 * x1 + x2 * x2) * (1.0f / 3.0f);
    float r = rsqrtf(var + 1e-6f);
    float y0 = x0 * r * postw[0];
    float y1 = x1 * r * postw[1];
    float y2 = x2 * r * postw[2];
    #pragma unroll
    for (int j = 0; j < 4; j++) {
        float g = gp[j * 3] * y0 + gp[j * 3 + 1] * y1 + gp[j * 3 + 2] * y2;
        float u = upw[j * 3] * y0 + upw[j * 3 + 1] * y1 + upw[j * 3 + 2] * y2;
        float sil = g / (1.0f + __expf(-g));
        float hh = sil * u;
        x0 += dp[0 * 4 + j] * hh;
        x1 += dp[1 * 4 + j] * hh;
        x2 += dp[2 * 4 + j] * hh;
    }
    float var2 = (x0 * x0 + x1 * x1 + x2 * x2) * (1.0f / 3.0f);
    float r2 = rsqrtf(var2 + 1e-6f);
    float z0 = x0 * r2 * finw[0];
    float z1 = x1 * r2 * finw[1];
    float z2 = x2 * r2 * finw[2];

    // each thread computes only the logits it stores: pair h, plus pair 4 on h==0
    float* o = out + (size_t)(b * 1024 + t) * 10;
    {
        int da = 2 * h, db = 2 * h + 1;
        float la = z0 * s_emb[3 * da] + z1 * s_emb[3 * da + 1] + z2 * s_emb[3 * da + 2];
        float lb = z0 * s_emb[3 * db] + z1 * s_emb[3 * db + 1] + z2 * s_emb[3 * db + 2];
        ((float2*)o)[h] = make_float2(la, lb);
        if (h == 0) {
            float l8 = z0 * s_emb[24] + z1 * s_emb[25] + z2 * s_emb[26];
            float l9 = z0 * s_emb[27] + z1 * s_emb[28] + z2 * s_emb[29];
            ((float2*)o)[4] = make_float2(l8, l9);
        }
    }
}

extern "C" void kernel_launch(void* const* d_in, const int* in_sizes, int n_in,
                              void* d_out, int out_size) {
    const int*   tok   = (const int*)d_in[0];
    const float* embed = (const float*)d_in[1];
    const float* inw   = (const float*)d_in[2];
    const float* postw = (const float*)d_in[3];
    const float* finw  = (const float*)d_in[4];
    const float* qnw   = (const float*)d_in[5];
    const float* knw   = (const float*)d_in[6];
    const float* kp    = (const float*)d_in[7];
    const float* vp    = (const float*)d_in[8];
    const float* qp    = (const float*)d_in[9];
    const float* op    = (const float*)d_in[10];
    const float* gp    = (const float*)d_in[11];
    const float* upw   = (const float*)d_in[12];
    const float* dp    = (const float*)d_in[13];
    float* out = (float*)d_out;

    k_all<<<128, 512>>>(tok, embed, inw, postw, finw, qnw, knw,
                        kp, vp, qp, op, gp, upw, dp, out);
}